// round 1
// baseline (speedup 1.0000x reference)
#include <cuda_runtime.h>
#include <cuda_bf16.h>
#include <math.h>

#define NTOK 4096
#define SQ   1024
#define BATCH 4
#define HIDD 2048
#define NH   16
#define NKV  4
#define HDIM 128
#define QKVD 3072   // (16+2*4)*128
#define INTD 8192
#define APITCH 132  // smem row pitch for K/V/Q tiles (floats)

// ---------------- scratch (static device memory; no allocations) ----------------
__device__ float g_xn  [(size_t)NTOK * HIDD];
__device__ float g_qkv [(size_t)NTOK * QKVD];
__device__ float g_attn[(size_t)NTOK * HIDD];
__device__ float g_h1  [(size_t)NTOK * HIDD];
__device__ float g_h2  [(size_t)NTOK * HIDD];
__device__ float g_gu  [(size_t)NTOK * 2 * INTD];
__device__ float g_act [(size_t)NTOK * INTD];

// ---------------- RMSNorm ----------------
__global__ void rmsnorm_kernel(const float* __restrict__ x, const float* __restrict__ w,
                               float* __restrict__ out) {
    int row = blockIdx.x;
    const float* xr = x + (size_t)row * HIDD;
    __shared__ float red[256];
    float4 vals[2];
    float s = 0.f;
#pragma unroll
    for (int i = 0; i < 2; i++) {
        float4 v = *(const float4*)(xr + (threadIdx.x + i * 256) * 4);
        vals[i] = v;
        s += v.x * v.x + v.y * v.y + v.z * v.z + v.w * v.w;
    }
    red[threadIdx.x] = s;
    __syncthreads();
    for (int off = 128; off > 0; off >>= 1) {
        if (threadIdx.x < off) red[threadIdx.x] += red[threadIdx.x + off];
        __syncthreads();
    }
    float inv = rsqrtf(red[0] / (float)HIDD + 1e-6f);
#pragma unroll
    for (int i = 0; i < 2; i++) {
        int c = (threadIdx.x + i * 256) * 4;
        float4 v = vals[i];
        float4 wv = *(const float4*)(w + c);
        float4 o = make_float4(v.x * inv * wv.x, v.y * inv * wv.y,
                               v.z * inv * wv.z, v.w * inv * wv.w);
        *(float4*)(out + (size_t)row * HIDD + c) = o;
    }
}

// ---------------- SGEMM 128x128x8, 256 threads, 8x8 per thread ----------------
// A: [M,K] row-major, B: [K,N] row-major, C = A@B (+ R if RES)
template <bool RES>
__global__ void sgemm128(const float* __restrict__ A, const float* __restrict__ B,
                         const float* __restrict__ R, float* __restrict__ C,
                         int M, int N, int K) {
    __shared__ float As[8][128];
    __shared__ float Bs[8][128];
    int tid = threadIdx.x;
    int bx = blockIdx.x;  // N tile
    int by = blockIdx.y;  // M tile
    const int rowC = (tid / 16) * 8;
    const int colC = (tid % 16) * 8;
    float acc[8][8] = {};
    const int innerRowA = tid / 2;         // 0..127
    const int innerColA = (tid % 2) * 4;   // 0,4
    const int innerRowB = tid / 32;        // 0..7
    const int innerColB = (tid % 32) * 4;  // 0..124
    const float* Ab = A + (size_t)(by * 128) * K;
    const float* Bb = B + bx * 128;
    for (int k0 = 0; k0 < K; k0 += 8) {
        float4 a4 = *(const float4*)(Ab + (size_t)innerRowA * K + k0 + innerColA);
        As[innerColA + 0][innerRowA] = a4.x;
        As[innerColA + 1][innerRowA] = a4.y;
        As[innerColA + 2][innerRowA] = a4.z;
        As[innerColA + 3][innerRowA] = a4.w;
        *(float4*)(&Bs[innerRowB][innerColB]) =
            *(const float4*)(Bb + (size_t)(k0 + innerRowB) * N + innerColB);
        __syncthreads();
#pragma unroll
        for (int kk = 0; kk < 8; kk++) {
            float4 a0 = *(const float4*)(&As[kk][rowC]);
            float4 a1 = *(const float4*)(&As[kk][rowC + 4]);
            float4 b0 = *(const float4*)(&Bs[kk][colC]);
            float4 b1 = *(const float4*)(&Bs[kk][colC + 4]);
            float ar[8] = {a0.x, a0.y, a0.z, a0.w, a1.x, a1.y, a1.z, a1.w};
            float br[8] = {b0.x, b0.y, b0.z, b0.w, b1.x, b1.y, b1.z, b1.w};
#pragma unroll
            for (int i = 0; i < 8; i++)
#pragma unroll
                for (int j = 0; j < 8; j++) acc[i][j] += ar[i] * br[j];
        }
        __syncthreads();
    }
#pragma unroll
    for (int i = 0; i < 8; i++) {
        int gr = by * 128 + rowC + i;
        float* Crow = C + (size_t)gr * N + bx * 128 + colC;
        const float* Rrow = RES ? (R + (size_t)gr * N + bx * 128 + colC) : nullptr;
#pragma unroll
        for (int j = 0; j < 8; j += 4) {
            float4 v = make_float4(acc[i][j], acc[i][j + 1], acc[i][j + 2], acc[i][j + 3]);
            if (RES) {
                float4 r4 = *(const float4*)(Rrow + j);
                v.x += r4.x; v.y += r4.y; v.z += r4.z; v.w += r4.w;
            }
            *(float4*)(Crow + j) = v;
        }
    }
}

// ---------------- RoPE (applied in-place to q and k slices of qkv) ----------------
__global__ void rope_kernel(float* __restrict__ qkv, const int* __restrict__ pos) {
    int tok = blockIdx.x;
    int p = pos[tok % SQ];
    // heads 0..15 = q, heads 16..19 = k, each head 128 floats, 64 rotation pairs
    for (int item = threadIdx.x; item < (NH + NKV) * 64; item += blockDim.x) {
        int head = item / 64;
        int d = item % 64;
        double freq = exp(-(double)d / 64.0 * log(10000.0));
        double ang = (double)p * freq;
        float c = (float)cos(ang);
        float s = (float)sin(ang);
        float* base = qkv + (size_t)tok * QKVD + head * HDIM;
        float t1 = base[d];
        float t2 = base[d + 64];
        base[d]      = t1 * c - t2 * s;
        base[d + 64] = t2 * c + t1 * s;
    }
}

// ---------------- Flash attention (fp32, causal, GQA) ----------------
// grid: (S/64, H, B), 256 threads (8 warps, 8 q-rows/warp)
__global__ void attn_kernel(const float* __restrict__ qkv, float* __restrict__ attn_out) {
    extern __shared__ float smem[];
    float* Qs = smem;                   // 64 * APITCH
    float* Ks = Qs + 64 * APITCH;       // 64 * APITCH
    float* Vs = Ks + 64 * APITCH;       // 64 * APITCH
    float* Ps = Vs + 64 * APITCH;       // 64 rows * 64 cols

    int qt = blockIdx.x, h = blockIdx.y, b = blockIdx.z;
    int kvh = h / (NH / NKV);
    int tid = threadIdx.x, w = tid / 32, lane = tid % 32;
    int tokQ0 = b * SQ + qt * 64;

    // load Q tile
    for (int i = tid; i < 64 * 32; i += 256) {
        int r = i / 32, c4 = (i % 32) * 4;
        *(float4*)(Qs + r * APITCH + c4) =
            *(const float4*)(qkv + (size_t)(tokQ0 + r) * QKVD + h * HDIM + c4);
    }

    float m[8], l[8], o[8][4];
#pragma unroll
    for (int r = 0; r < 8; r++) {
        m[r] = -1e30f; l[r] = 0.f;
        o[r][0] = o[r][1] = o[r][2] = o[r][3] = 0.f;
    }
    const float scale = 0.08838834764831845f;  // 1/sqrt(128)

    for (int kt = 0; kt <= qt; kt++) {
        __syncthreads();  // protect K/V (and Q on first iter)
        int tokK0 = b * SQ + kt * 64;
        for (int i = tid; i < 64 * 32; i += 256) {
            int r = i / 32, c4 = (i % 32) * 4;
            const float* base = qkv + (size_t)(tokK0 + r) * QKVD;
            *(float4*)(Ks + r * APITCH + c4) =
                *(const float4*)(base + NH * HDIM + kvh * HDIM + c4);
            *(float4*)(Vs + r * APITCH + c4) =
                *(const float4*)(base + (NH + NKV) * HDIM + kvh * HDIM + c4);
        }
        __syncthreads();

        bool diag = (kt == qt);
        for (int r = 0; r < 8; r++) {
            int qi = w * 8 + r;
            const float4* q4 = (const float4*)(Qs + qi * APITCH);
            const float4* k14 = (const float4*)(Ks + lane * APITCH);
            const float4* k24 = (const float4*)(Ks + (lane + 32) * APITCH);
            float s1 = 0.f, s2 = 0.f;
#pragma unroll 8
            for (int kk = 0; kk < 32; kk++) {
                float4 qv = q4[kk], a = k14[kk], c = k24[kk];
                s1 += qv.x * a.x + qv.y * a.y + qv.z * a.z + qv.w * a.w;
                s2 += qv.x * c.x + qv.y * c.y + qv.z * c.z + qv.w * c.w;
            }
            s1 *= scale; s2 *= scale;
            if (diag) {
                if (lane > qi) s1 = -1e30f;
                if (lane + 32 > qi) s2 = -1e30f;
            }
            float mx = fmaxf(s1, s2);
#pragma unroll
            for (int off = 16; off > 0; off >>= 1)
                mx = fmaxf(mx, __shfl_xor_sync(0xffffffffu, mx, off));
            float mnew = fmaxf(m[r], mx);
            float p1 = expf(s1 - mnew);
            float p2 = expf(s2 - mnew);
            float corr = expf(m[r] - mnew);
            float rowsum = p1 + p2;
#pragma unroll
            for (int off = 16; off > 0; off >>= 1)
                rowsum += __shfl_xor_sync(0xffffffffu, rowsum, off);
            l[r] = l[r] * corr + rowsum;
            m[r] = mnew;
            o[r][0] *= corr; o[r][1] *= corr; o[r][2] *= corr; o[r][3] *= corr;
            Ps[qi * 64 + lane] = p1;
            Ps[qi * 64 + lane + 32] = p2;
        }
        __syncwarp();
        // PV: lane owns output cols [lane*4, lane*4+4)
        for (int j = 0; j < 64; j++) {
            float4 v4 = *(const float4*)(Vs + j * APITCH + lane * 4);
#pragma unroll
            for (int r = 0; r < 8; r++) {
                float p = Ps[(w * 8 + r) * 64 + j];
                o[r][0] += p * v4.x; o[r][1] += p * v4.y;
                o[r][2] += p * v4.z; o[r][3] += p * v4.w;
            }
        }
    }

#pragma unroll
    for (int r = 0; r < 8; r++) {
        int qi = w * 8 + r;
        float inv = 1.f / l[r];
        float4 v = make_float4(o[r][0] * inv, o[r][1] * inv, o[r][2] * inv, o[r][3] * inv);
        *(float4*)(attn_out + (size_t)(tokQ0 + qi) * HIDD + h * HDIM + lane * 4) = v;
    }
}

// ---------------- SiLU(gate) * up ----------------
__global__ void silu_kernel(const float* __restrict__ gu, float* __restrict__ act) {
    size_t n4 = (size_t)NTOK * INTD / 4;
    for (size_t idx = (size_t)blockIdx.x * blockDim.x + threadIdx.x; idx < n4;
         idx += (size_t)gridDim.x * blockDim.x) {
        size_t t = idx / (INTD / 4);
        size_t c = (idx % (INTD / 4)) * 4;
        float4 g = *(const float4*)(gu + t * (2 * INTD) + c);
        float4 u = *(const float4*)(gu + t * (2 * INTD) + INTD + c);
        float4 o;
        o.x = g.x / (1.f + expf(-g.x)) * u.x;
        o.y = g.y / (1.f + expf(-g.y)) * u.y;
        o.z = g.z / (1.f + expf(-g.z)) * u.z;
        o.w = g.w / (1.f + expf(-g.w)) * u.w;
        *(float4*)(act + idx * 4) = o;
    }
}

#define ATTN_SMEM ((3 * 64 * APITCH + 64 * 64) * 4)

extern "C" void kernel_launch(void* const* d_in, const int* in_sizes, int n_in,
                              void* d_out, int out_size) {
    const float* x    = (const float*)d_in[0];
    const float* ln1  = (const float*)d_in[1];
    const float* wqkv = (const float*)d_in[2];
    const float* wo   = (const float*)d_in[3];
    const float* ln2  = (const float*)d_in[4];
    const float* wgu  = (const float*)d_in[5];
    const float* wdn  = (const float*)d_in[6];
    const int*   pos  = (const int*)d_in[7];
    float* out = (float*)d_out;

    void *xn, *qkv, *attn, *h1, *h2, *gu, *act;
    cudaGetSymbolAddress(&xn, g_xn);
    cudaGetSymbolAddress(&qkv, g_qkv);
    cudaGetSymbolAddress(&attn, g_attn);
    cudaGetSymbolAddress(&h1, g_h1);
    cudaGetSymbolAddress(&h2, g_h2);
    cudaGetSymbolAddress(&gu, g_gu);
    cudaGetSymbolAddress(&act, g_act);

    cudaFuncSetAttribute(attn_kernel, cudaFuncAttributeMaxDynamicSharedMemorySize, ATTN_SMEM);

    // 1. h = rmsnorm(x, ln1)
    rmsnorm_kernel<<<NTOK, 256>>>(x, ln1, (float*)xn);
    // 2. qkv = h @ wqkv
    {
        dim3 g(QKVD / 128, NTOK / 128);
        sgemm128<false><<<g, 256>>>((const float*)xn, wqkv, nullptr, (float*)qkv,
                                    NTOK, QKVD, HIDD);
    }
    // 3. RoPE on q,k
    rope_kernel<<<NTOK, 256>>>((float*)qkv, pos);
    // 4. attention
    {
        dim3 g(SQ / 64, NH, BATCH);
        attn_kernel<<<g, 256, ATTN_SMEM>>>((const float*)qkv, (float*)attn);
    }
    // 5. h1 = x + attn @ wo
    {
        dim3 g(HIDD / 128, NTOK / 128);
        sgemm128<true><<<g, 256>>>((const float*)attn, wo, x, (float*)h1,
                                   NTOK, HIDD, HIDD);
    }
    // 6. h2 = rmsnorm(h1, ln2)
    rmsnorm_kernel<<<NTOK, 256>>>((const float*)h1, ln2, (float*)h2);
    // 7. gu = h2 @ w_gate_up
    {
        dim3 g(2 * INTD / 128, NTOK / 128);
        sgemm128<false><<<g, 256>>>((const float*)h2, wgu, nullptr, (float*)gu,
                                    NTOK, 2 * INTD, HIDD);
    }
    // 8. act = silu(gate)*up
    silu_kernel<<<32768, 256>>>((const float*)gu, (float*)act);
    // 9. out = h1 + act @ w_down
    {
        dim3 g(HIDD / 128, NTOK / 128);
        sgemm128<true><<<g, 256>>>((const float*)act, wdn, (const float*)h1, out,
                                   NTOK, HIDD, INTD);
    }
}

// round 2
// speedup vs baseline: 2.0657x; 2.0657x over previous
#include <cuda_runtime.h>
#include <cuda_bf16.h>
#include <math.h>
#include <stdint.h>

#define NTOK 4096
#define SQ   1024
#define BATCH 4
#define HIDD 2048
#define NH   16
#define NKV  4
#define HDIM 128
#define QKVD 3072   // (16+2*4)*128
#define INTD 8192
#define APITCH 132  // smem row pitch for attention tiles (floats)

// ---------------- scratch (static device memory; no allocations) ----------------
__device__ float g_xn  [(size_t)NTOK * HIDD];
__device__ float g_qkv [(size_t)NTOK * QKVD];
__device__ float g_attn[(size_t)NTOK * HIDD];
__device__ float g_h1  [(size_t)NTOK * HIDD];
__device__ float g_h2  [(size_t)NTOK * HIDD];
__device__ float g_gu  [(size_t)NTOK * 2 * INTD];
__device__ float g_act [(size_t)NTOK * INTD];

// ---------------- helpers ----------------
__device__ __forceinline__ float tf32rnd(float x) {
    uint32_t u;
    asm("cvt.rna.tf32.f32 %0, %1;" : "=r"(u) : "f"(x));
    return __uint_as_float(u);
}

__device__ __forceinline__ void mma_tf32(float* c, const uint32_t* a, const uint32_t* b) {
    asm volatile(
        "mma.sync.aligned.m16n8k8.row.col.f32.tf32.tf32.f32 "
        "{%0,%1,%2,%3}, {%4,%5,%6,%7}, {%8,%9}, {%0,%1,%2,%3};\n"
        : "+f"(c[0]), "+f"(c[1]), "+f"(c[2]), "+f"(c[3])
        : "r"(a[0]), "r"(a[1]), "r"(a[2]), "r"(a[3]), "r"(b[0]), "r"(b[1]));
}

// ---------------- RMSNorm ----------------
__global__ void rmsnorm_kernel(const float* __restrict__ x, const float* __restrict__ w,
                               float* __restrict__ out) {
    int row = blockIdx.x;
    const float* xr = x + (size_t)row * HIDD;
    __shared__ float red[256];
    float4 vals[2];
    float s = 0.f;
#pragma unroll
    for (int i = 0; i < 2; i++) {
        float4 v = *(const float4*)(xr + (threadIdx.x + i * 256) * 4);
        vals[i] = v;
        s += v.x * v.x + v.y * v.y + v.z * v.z + v.w * v.w;
    }
    red[threadIdx.x] = s;
    __syncthreads();
    for (int off = 128; off > 0; off >>= 1) {
        if (threadIdx.x < off) red[threadIdx.x] += red[threadIdx.x + off];
        __syncthreads();
    }
    float inv = rsqrtf(red[0] / (float)HIDD + 1e-6f);
#pragma unroll
    for (int i = 0; i < 2; i++) {
        int c = (threadIdx.x + i * 256) * 4;
        float4 v = vals[i];
        float4 wv = *(const float4*)(w + c);
        float4 o = make_float4(v.x * inv * wv.x, v.y * inv * wv.y,
                               v.z * inv * wv.z, v.w * inv * wv.w);
        *(float4*)(out + (size_t)row * HIDD + c) = o;
    }
}

// ---------------- tf32 tensor-core GEMM: 128x128x32 tile, 256 threads ----------------
// A: [M,K] row-major, B: [K,N] row-major, C = A@B (+ R if RES)
// smem: double-buffered As[2][32][128] (k-major, XOR swizzled) + Bs[2][32][128]
#define SWZ(idx, k) ((idx) ^ (((k) & 3) << 3))
#define GEMM_SMEM (4 * 32 * 128 * 4)

template <bool RES>
__global__ __launch_bounds__(256) void tf32gemm(const float* __restrict__ A,
                                                const float* __restrict__ B,
                                                const float* __restrict__ R,
                                                float* __restrict__ C,
                                                int M, int N, int K) {
    extern __shared__ float sm[];
    float* AsBase = sm;                // [2][4096]
    float* BsBase = sm + 2 * 4096;     // [2][4096]

    const int tid = threadIdx.x;
    const int lane = tid & 31, warp = tid >> 5;
    const int wr = warp >> 2, wc = warp & 3;     // warp grid 2x4, warp tile 64x32
    const int g = lane >> 2, tg = lane & 3;
    const int bx = blockIdx.x, by = blockIdx.y;

    const float* Ab = A + (size_t)(by * 128) * K;
    const float* Bb = B + (size_t)(bx * 128);

    // A staging: thread -> row mA, 16 consecutive k starting at kqA
    const int mA = tid >> 1;
    const int kqA = (tid & 1) * 16;

    float4 ra[4], rb[4];
    float acc[4][4][4];
#pragma unroll
    for (int i = 0; i < 4; i++)
#pragma unroll
        for (int j = 0; j < 4; j++)
#pragma unroll
            for (int z = 0; z < 4; z++) acc[i][j][z] = 0.f;

    const int nk = K >> 5;

    // ---- prologue: load tile 0 ----
    {
        const float* p = Ab + (size_t)mA * K + kqA;
        ra[0] = *(const float4*)(p);
        ra[1] = *(const float4*)(p + 4);
        ra[2] = *(const float4*)(p + 8);
        ra[3] = *(const float4*)(p + 12);
#pragma unroll
        for (int i = 0; i < 4; i++) {
            int f = tid + i * 256;
            rb[i] = *(const float4*)(Bb + (size_t)(f >> 5) * N + (f & 31) * 4);
        }
    }
    // store tile 0 into buffer 0
    {
        float* As = AsBase;
        float* Bs = BsBase;
        const float* rav = (const float*)ra;
#pragma unroll
        for (int j = 0; j < 16; j++) {
            int k = kqA + j;
            As[k * 128 + SWZ(mA, k)] = tf32rnd(rav[j]);
        }
#pragma unroll
        for (int i = 0; i < 4; i++) {
            int f = tid + i * 256;
            int k = f >> 5, n = (f & 31) * 4;
            float4 v = rb[i];
            v.x = tf32rnd(v.x); v.y = tf32rnd(v.y);
            v.z = tf32rnd(v.z); v.w = tf32rnd(v.w);
            *(float4*)(Bs + k * 128 + SWZ(n, k)) = v;
        }
    }
    __syncthreads();

    for (int it = 0; it < nk; it++) {
        int s = it & 1;
        // prefetch next tile into registers
        if (it + 1 < nk) {
            int k0 = (it + 1) << 5;
            const float* p = Ab + (size_t)mA * K + k0 + kqA;
            ra[0] = *(const float4*)(p);
            ra[1] = *(const float4*)(p + 4);
            ra[2] = *(const float4*)(p + 8);
            ra[3] = *(const float4*)(p + 12);
#pragma unroll
            for (int i = 0; i < 4; i++) {
                int f = tid + i * 256;
                rb[i] = *(const float4*)(Bb + (size_t)(k0 + (f >> 5)) * N + (f & 31) * 4);
            }
        }
        // compute from buffer s
        {
            const float* As = AsBase + s * 4096;
            const float* Bs = BsBase + s * 4096;
#pragma unroll
            for (int kk = 0; kk < 32; kk += 8) {
                const int k0 = kk + tg, k1 = kk + tg + 4;
                uint32_t af[4][4];
#pragma unroll
                for (int mf = 0; mf < 4; mf++) {
                    int m = wr * 64 + mf * 16 + g;
                    af[mf][0] = __float_as_uint(As[k0 * 128 + SWZ(m, k0)]);
                    af[mf][1] = __float_as_uint(As[k0 * 128 + SWZ(m + 8, k0)]);
                    af[mf][2] = __float_as_uint(As[k1 * 128 + SWZ(m, k1)]);
                    af[mf][3] = __float_as_uint(As[k1 * 128 + SWZ(m + 8, k1)]);
                }
                uint32_t bf[4][2];
#pragma unroll
                for (int nf = 0; nf < 4; nf++) {
                    int n = wc * 32 + nf * 8 + g;
                    bf[nf][0] = __float_as_uint(Bs[k0 * 128 + SWZ(n, k0)]);
                    bf[nf][1] = __float_as_uint(Bs[k1 * 128 + SWZ(n, k1)]);
                }
#pragma unroll
                for (int mf = 0; mf < 4; mf++)
#pragma unroll
                    for (int nf = 0; nf < 4; nf++)
                        mma_tf32(acc[mf][nf], af[mf], bf[nf]);
            }
        }
        // store prefetched tile into the other buffer
        if (it + 1 < nk) {
            float* As = AsBase + (1 - s) * 4096;
            float* Bs = BsBase + (1 - s) * 4096;
            const float* rav = (const float*)ra;
#pragma unroll
            for (int j = 0; j < 16; j++) {
                int k = kqA + j;
                As[k * 128 + SWZ(mA, k)] = tf32rnd(rav[j]);
            }
#pragma unroll
            for (int i = 0; i < 4; i++) {
                int f = tid + i * 256;
                int k = f >> 5, n = (f & 31) * 4;
                float4 v = rb[i];
                v.x = tf32rnd(v.x); v.y = tf32rnd(v.y);
                v.z = tf32rnd(v.z); v.w = tf32rnd(v.w);
                *(float4*)(Bs + k * 128 + SWZ(n, k)) = v;
            }
            __syncthreads();
        }
    }

    // ---- epilogue ----
#pragma unroll
    for (int mf = 0; mf < 4; mf++) {
#pragma unroll
        for (int half = 0; half < 2; half++) {
            int row = by * 128 + wr * 64 + mf * 16 + g + half * 8;
            float* Crow = C + (size_t)row * N + bx * 128 + wc * 32;
            const float* Rrow = RES ? (R + (size_t)row * N + bx * 128 + wc * 32) : nullptr;
#pragma unroll
            for (int nf = 0; nf < 4; nf++) {
                int col = nf * 8 + tg * 2;
                float2 v = make_float2(acc[mf][nf][half * 2 + 0],
                                       acc[mf][nf][half * 2 + 1]);
                if (RES) {
                    v.x += Rrow[col];
                    v.y += Rrow[col + 1];
                }
                *(float2*)(Crow + col) = v;
            }
        }
    }
}

// ---------------- RoPE (applied in-place to q and k slices of qkv) ----------------
__global__ void rope_kernel(float* __restrict__ qkv, const int* __restrict__ pos) {
    int tok = blockIdx.x;
    int p = pos[tok % SQ];
    for (int item = threadIdx.x; item < (NH + NKV) * 64; item += blockDim.x) {
        int head = item / 64;
        int d = item % 64;
        double freq = exp(-(double)d / 64.0 * log(10000.0));
        double ang = (double)p * freq;
        float c = (float)cos(ang);
        float s = (float)sin(ang);
        float* base = qkv + (size_t)tok * QKVD + head * HDIM;
        float t1 = base[d];
        float t2 = base[d + 64];
        base[d]      = t1 * c - t2 * s;
        base[d + 64] = t2 * c + t1 * s;
    }
}

// ---------------- Flash attention (fp32, causal, GQA) ----------------
__global__ void attn_kernel(const float* __restrict__ qkv, float* __restrict__ attn_out) {
    extern __shared__ float smem[];
    float* Qs = smem;
    float* Ks = Qs + 64 * APITCH;
    float* Vs = Ks + 64 * APITCH;
    float* Ps = Vs + 64 * APITCH;

    int qt = blockIdx.x, h = blockIdx.y, b = blockIdx.z;
    int kvh = h / (NH / NKV);
    int tid = threadIdx.x, w = tid / 32, lane = tid % 32;
    int tokQ0 = b * SQ + qt * 64;

    for (int i = tid; i < 64 * 32; i += 256) {
        int r = i / 32, c4 = (i % 32) * 4;
        *(float4*)(Qs + r * APITCH + c4) =
            *(const float4*)(qkv + (size_t)(tokQ0 + r) * QKVD + h * HDIM + c4);
    }

    float m[8], l[8], o[8][4];
#pragma unroll
    for (int r = 0; r < 8; r++) {
        m[r] = -1e30f; l[r] = 0.f;
        o[r][0] = o[r][1] = o[r][2] = o[r][3] = 0.f;
    }
    const float scale = 0.08838834764831845f;

    for (int kt = 0; kt <= qt; kt++) {
        __syncthreads();
        int tokK0 = b * SQ + kt * 64;
        for (int i = tid; i < 64 * 32; i += 256) {
            int r = i / 32, c4 = (i % 32) * 4;
            const float* base = qkv + (size_t)(tokK0 + r) * QKVD;
            *(float4*)(Ks + r * APITCH + c4) =
                *(const float4*)(base + NH * HDIM + kvh * HDIM + c4);
            *(float4*)(Vs + r * APITCH + c4) =
                *(const float4*)(base + (NH + NKV) * HDIM + kvh * HDIM + c4);
        }
        __syncthreads();

        bool diag = (kt == qt);
        for (int r = 0; r < 8; r++) {
            int qi = w * 8 + r;
            const float4* q4 = (const float4*)(Qs + qi * APITCH);
            const float4* k14 = (const float4*)(Ks + lane * APITCH);
            const float4* k24 = (const float4*)(Ks + (lane + 32) * APITCH);
            float s1 = 0.f, s2 = 0.f;
#pragma unroll 8
            for (int kk = 0; kk < 32; kk++) {
                float4 qv = q4[kk], a = k14[kk], c = k24[kk];
                s1 += qv.x * a.x + qv.y * a.y + qv.z * a.z + qv.w * a.w;
                s2 += qv.x * c.x + qv.y * c.y + qv.z * c.z + qv.w * c.w;
            }
            s1 *= scale; s2 *= scale;
            if (diag) {
                if (lane > qi) s1 = -1e30f;
                if (lane + 32 > qi) s2 = -1e30f;
            }
            float mx = fmaxf(s1, s2);
#pragma unroll
            for (int off = 16; off > 0; off >>= 1)
                mx = fmaxf(mx, __shfl_xor_sync(0xffffffffu, mx, off));
            float mnew = fmaxf(m[r], mx);
            float p1 = expf(s1 - mnew);
            float p2 = expf(s2 - mnew);
            float corr = expf(m[r] - mnew);
            float rowsum = p1 + p2;
#pragma unroll
            for (int off = 16; off > 0; off >>= 1)
                rowsum += __shfl_xor_sync(0xffffffffu, rowsum, off);
            l[r] = l[r] * corr + rowsum;
            m[r] = mnew;
            o[r][0] *= corr; o[r][1] *= corr; o[r][2] *= corr; o[r][3] *= corr;
            Ps[qi * 64 + lane] = p1;
            Ps[qi * 64 + lane + 32] = p2;
        }
        __syncwarp();
        for (int j = 0; j < 64; j++) {
            float4 v4 = *(const float4*)(Vs + j * APITCH + lane * 4);
#pragma unroll
            for (int r = 0; r < 8; r++) {
                float p = Ps[(w * 8 + r) * 64 + j];
                o[r][0] += p * v4.x; o[r][1] += p * v4.y;
                o[r][2] += p * v4.z; o[r][3] += p * v4.w;
            }
        }
    }

#pragma unroll
    for (int r = 0; r < 8; r++) {
        int qi = w * 8 + r;
        float inv = 1.f / l[r];
        float4 v = make_float4(o[r][0] * inv, o[r][1] * inv, o[r][2] * inv, o[r][3] * inv);
        *(float4*)(attn_out + (size_t)(tokQ0 + qi) * HIDD + h * HDIM + lane * 4) = v;
    }
}

// ---------------- SiLU(gate) * up ----------------
__global__ void silu_kernel(const float* __restrict__ gu, float* __restrict__ act) {
    size_t n4 = (size_t)NTOK * INTD / 4;
    for (size_t idx = (size_t)blockIdx.x * blockDim.x + threadIdx.x; idx < n4;
         idx += (size_t)gridDim.x * blockDim.x) {
        size_t t = idx / (INTD / 4);
        size_t c = (idx % (INTD / 4)) * 4;
        float4 g = *(const float4*)(gu + t * (2 * INTD) + c);
        float4 u = *(const float4*)(gu + t * (2 * INTD) + INTD + c);
        float4 o;
        o.x = g.x / (1.f + expf(-g.x)) * u.x;
        o.y = g.y / (1.f + expf(-g.y)) * u.y;
        o.z = g.z / (1.f + expf(-g.z)) * u.z;
        o.w = g.w / (1.f + expf(-g.w)) * u.w;
        *(float4*)(act + idx * 4) = o;
    }
}

#define ATTN_SMEM ((3 * 64 * APITCH + 64 * 64) * 4)

extern "C" void kernel_launch(void* const* d_in, const int* in_sizes, int n_in,
                              void* d_out, int out_size) {
    const float* x    = (const float*)d_in[0];
    const float* ln1  = (const float*)d_in[1];
    const float* wqkv = (const float*)d_in[2];
    const float* wo   = (const float*)d_in[3];
    const float* ln2  = (const float*)d_in[4];
    const float* wgu  = (const float*)d_in[5];
    const float* wdn  = (const float*)d_in[6];
    const int*   pos  = (const int*)d_in[7];
    float* out = (float*)d_out;

    void *xn, *qkv, *attn, *h1, *h2, *gu, *act;
    cudaGetSymbolAddress(&xn, g_xn);
    cudaGetSymbolAddress(&qkv, g_qkv);
    cudaGetSymbolAddress(&attn, g_attn);
    cudaGetSymbolAddress(&h1, g_h1);
    cudaGetSymbolAddress(&h2, g_h2);
    cudaGetSymbolAddress(&gu, g_gu);
    cudaGetSymbolAddress(&act, g_act);

    cudaFuncSetAttribute(attn_kernel, cudaFuncAttributeMaxDynamicSharedMemorySize, ATTN_SMEM);
    cudaFuncSetAttribute(tf32gemm<false>, cudaFuncAttributeMaxDynamicSharedMemorySize, GEMM_SMEM);
    cudaFuncSetAttribute(tf32gemm<true>,  cudaFuncAttributeMaxDynamicSharedMemorySize, GEMM_SMEM);

    // 1. h = rmsnorm(x, ln1)
    rmsnorm_kernel<<<NTOK, 256>>>(x, ln1, (float*)xn);
    // 2. qkv = h @ wqkv
    {
        dim3 g(QKVD / 128, NTOK / 128);
        tf32gemm<false><<<g, 256, GEMM_SMEM>>>((const float*)xn, wqkv, nullptr,
                                               (float*)qkv, NTOK, QKVD, HIDD);
    }
    // 3. RoPE on q,k
    rope_kernel<<<NTOK, 256>>>((float*)qkv, pos);
    // 4. attention
    {
        dim3 g(SQ / 64, NH, BATCH);
        attn_kernel<<<g, 256, ATTN_SMEM>>>((const float*)qkv, (float*)attn);
    }
    // 5. h1 = x + attn @ wo
    {
        dim3 g(HIDD / 128, NTOK / 128);
        tf32gemm<true><<<g, 256, GEMM_SMEM>>>((const float*)attn, wo, x,
                                              (float*)h1, NTOK, HIDD, HIDD);
    }
    // 6. h2 = rmsnorm(h1, ln2)
    rmsnorm_kernel<<<NTOK, 256>>>((const float*)h1, ln2, (float*)h2);
    // 7. gu = h2 @ w_gate_up
    {
        dim3 g(2 * INTD / 128, NTOK / 128);
        tf32gemm<false><<<g, 256, GEMM_SMEM>>>((const float*)h2, wgu, nullptr,
                                               (float*)gu, NTOK, 2 * INTD, HIDD);
    }
    // 8. act = silu(gate)*up
    silu_kernel<<<32768, 256>>>((const float*)gu, (float*)act);
    // 9. out = h1 + act @ w_down
    {
        dim3 g(HIDD / 128, NTOK / 128);
        tf32gemm<true><<<g, 256, GEMM_SMEM>>>((const float*)act, wdn,
                                              (const float*)h1, out, NTOK, HIDD, INTD);
    }
}

// round 4
// speedup vs baseline: 3.2785x; 1.5871x over previous
#include <cuda_runtime.h>
#include <cuda_bf16.h>
#include <math.h>
#include <stdint.h>

#define NTOK 4096
#define SQ   1024
#define BATCH 4
#define HIDD 2048
#define NH   16
#define NKV  4
#define HDIM 128
#define QKVD 3072   // (16+2*4)*128
#define INTD 8192
#define APITCH 132  // smem row pitch for attention tiles (floats)

// ---------------- scratch (static device memory; no allocations) ----------------
__device__ float g_xn  [(size_t)NTOK * HIDD];
__device__ float g_qkv [(size_t)NTOK * QKVD];
__device__ float g_attn[(size_t)NTOK * HIDD];
__device__ float g_h1  [(size_t)NTOK * HIDD];
__device__ float g_h2  [(size_t)NTOK * HIDD];
__device__ float g_gu  [(size_t)NTOK * 2 * INTD];
__device__ float g_act [(size_t)NTOK * INTD];
// transposed + tf32-rounded weights [N, K] K-major
__device__ float g_wqkvT [(size_t)QKVD * HIDD];
__device__ float g_woT   [(size_t)HIDD * HIDD];
__device__ float g_wguT  [(size_t)2 * INTD * HIDD];
__device__ float g_wdnT  [(size_t)HIDD * INTD];

// ---------------- helpers ----------------
__device__ __forceinline__ float tf32rnd(float x) {
    uint32_t u;
    asm("cvt.rna.tf32.f32 %0, %1;" : "=r"(u) : "f"(x));
    return __uint_as_float(u);
}

__device__ __forceinline__ uint32_t smem_u32(const void* p) {
    uint32_t a;
    asm("{ .reg .u64 t; cvta.to.shared.u64 t, %1; cvt.u32.u64 %0, t; }"
        : "=r"(a) : "l"(p));
    return a;
}

__device__ __forceinline__ uint32_t lds_u32(uint32_t a) {
    uint32_t v;
    asm volatile("ld.shared.b32 %0, [%1];" : "=r"(v) : "r"(a));
    return v;
}

#define SWZ128(o) ((o) ^ (((o) >> 3) & 0x70))

#define CP_ASYNC16(dst, src) \
    asm volatile("cp.async.cg.shared.global [%0], [%1], 16;" :: "r"(dst), "l"(src) : "memory")
#define CP_COMMIT() asm volatile("cp.async.commit_group;" ::: "memory")

__device__ __forceinline__ void mma_tf32(float* c, const uint32_t* a, const uint32_t* b) {
    asm volatile(
        "mma.sync.aligned.m16n8k8.row.col.f32.tf32.tf32.f32 "
        "{%0,%1,%2,%3}, {%4,%5,%6,%7}, {%8,%9}, {%0,%1,%2,%3};\n"
        : "+f"(c[0]), "+f"(c[1]), "+f"(c[2]), "+f"(c[3])
        : "r"(a[0]), "r"(a[1]), "r"(a[2]), "r"(a[3]), "r"(b[0]), "r"(b[1]));
}

// ---------------- HMMA tf32 GEMM: tile 256(M) x 128(N), kc=32, 3-stage cp.async --------
#define TM 256
#define TN 128
#define KC 32
#define NSTG 3
#define ASZ (TM * KC * 4)     // 32768 B
#define BSZ (TN * KC * 4)     // 16384 B
#define STGB (ASZ + BSZ)      // 49152 B
#define GEMM_SMEM_TC (NSTG * STGB)  // 147456 B

// A [M,K] row-major (tf32-rounded), Bt [N,K] row-major (tf32-rounded)
// C[M,N] = A @ Bt^T (+ R).  grid = (M/256, N/128), 256 threads.
template <bool RES>
__global__ __launch_bounds__(256, 1) void tc_gemm(const float* __restrict__ A,
                                                  const float* __restrict__ Bt,
                                                  const float* __restrict__ R,
                                                  float* __restrict__ C,
                                                  int N, int K) {
    extern __shared__ char smc[];
    const uint32_t sb = smem_u32(smc);
    const int tid = threadIdx.x;
    const int lane = tid & 31, w = tid >> 5;
    const int wm = w >> 1, wn = w & 1;          // warp grid 4x2, warp tile 64x64
    const int g = lane >> 2, tg = lane & 3;
    const int by = blockIdx.x, bx = blockIdx.y;

    const float* Ab = A + (size_t)(by * TM) * K;
    const float* Bb = Bt + (size_t)(bx * TN) * K;
    const int nk = K / KC;

    const int lrow = tid >> 3;      // 0..31
    const int lseg = tid & 7;       // 0..7 (16B segment within 128B row)

    float acc[4][8][4];
#pragma unroll
    for (int i = 0; i < 4; i++)
#pragma unroll
        for (int j = 0; j < 8; j++)
#pragma unroll
            for (int z = 0; z < 4; z++) acc[i][j][z] = 0.f;

    auto load_chunk = [&](int j) {
        uint32_t st = sb + (j % NSTG) * STGB;
#pragma unroll
        for (int i = 0; i < 8; i++) {
            int r = i * 32 + lrow;
            uint32_t off = (uint32_t)(r * 128 + lseg * 16);
            CP_ASYNC16(st + SWZ128(off), Ab + (size_t)r * K + j * KC + lseg * 4);
        }
        uint32_t stB = st + ASZ;
#pragma unroll
        for (int i = 0; i < 4; i++) {
            int r = i * 32 + lrow;
            uint32_t off = (uint32_t)(r * 128 + lseg * 16);
            CP_ASYNC16(stB + SWZ128(off), Bb + (size_t)r * K + j * KC + lseg * 4);
        }
        CP_COMMIT();
    };

    for (int j = 0; j < NSTG - 1 && j < nk; j++) load_chunk(j);

    for (int it = 0; it < nk; it++) {
        if (it < nk - 1)
            asm volatile("cp.async.wait_group 1;" ::: "memory");
        else
            asm volatile("cp.async.wait_group 0;" ::: "memory");
        __syncthreads();
        if (it + NSTG - 1 < nk) load_chunk(it + NSTG - 1);

        const uint32_t sA = sb + (it % NSTG) * STGB;
        const uint32_t sB = sA + ASZ;
#pragma unroll
        for (int kk = 0; kk < 4; kk++) {
            const int k0 = kk * 8;
            uint32_t af[4][4];
#pragma unroll
            for (int mf = 0; mf < 4; mf++) {
                int r0 = wm * 64 + mf * 16 + g;
                uint32_t ro = sA + r0 * 128;
                uint32_t kx = (uint32_t)((r0 & 7) << 4);
                uint32_t kl = ((uint32_t)((k0 + tg) * 4)) ^ kx;
                uint32_t kh = ((uint32_t)((k0 + tg + 4) * 4)) ^ kx;
                af[mf][0] = lds_u32(ro + kl);
                af[mf][1] = lds_u32(ro + 1024 + kl);   // row+8: same (row&7)
                af[mf][2] = lds_u32(ro + kh);
                af[mf][3] = lds_u32(ro + 1024 + kh);
            }
            uint32_t bf[8][2];
#pragma unroll
            for (int nf = 0; nf < 8; nf++) {
                int r = wn * 64 + nf * 8 + g;
                uint32_t ro = sB + r * 128;
                uint32_t kx = (uint32_t)((r & 7) << 4);
                bf[nf][0] = lds_u32(ro + (((uint32_t)((k0 + tg) * 4)) ^ kx));
                bf[nf][1] = lds_u32(ro + (((uint32_t)((k0 + tg + 4) * 4)) ^ kx));
            }
#pragma unroll
            for (int mf = 0; mf < 4; mf++)
#pragma unroll
                for (int nf = 0; nf < 8; nf++)
                    mma_tf32(acc[mf][nf], af[mf], bf[nf]);
        }
        __syncthreads();
    }

    // epilogue
#pragma unroll
    for (int mf = 0; mf < 4; mf++) {
#pragma unroll
        for (int half = 0; half < 2; half++) {
            int row = by * TM + wm * 64 + mf * 16 + g + half * 8;
            float* Crow = C + (size_t)row * N + bx * TN + wn * 64;
            const float* Rrow = RES ? (R + (size_t)row * N + bx * TN + wn * 64)
                                    : (const float*)0;
#pragma unroll
            for (int nf = 0; nf < 8; nf++) {
                int col = nf * 8 + tg * 2;
                float2 v = make_float2(acc[mf][nf][half * 2 + 0],
                                       acc[mf][nf][half * 2 + 1]);
                if (RES) {
                    v.x += Rrow[col];
                    v.y += Rrow[col + 1];
                }
                *(float2*)(Crow + col) = v;
            }
        }
    }
}

// ---------------- weight transpose + tf32 round: in [K,N] -> out [N,K] ----------------
__global__ void transpose_round_kernel(const float* __restrict__ in,
                                       float* __restrict__ out, int K, int N) {
    __shared__ float t[32][33];
    int n0 = blockIdx.x * 32, k0 = blockIdx.y * 32;
    int tx = threadIdx.x, ty = threadIdx.y;
#pragma unroll
    for (int r = 0; r < 4; r++)
        t[ty + r * 8][tx] = in[(size_t)(k0 + ty + r * 8) * N + n0 + tx];
    __syncthreads();
#pragma unroll
    for (int r = 0; r < 4; r++)
        out[(size_t)(n0 + ty + r * 8) * K + k0 + tx] = tf32rnd(t[tx][ty + r * 8]);
}

// ---------------- RMSNorm (output tf32-rounded; feeds GEMM A) ----------------
__global__ void rmsnorm_kernel(const float* __restrict__ x, const float* __restrict__ w,
                               float* __restrict__ out) {
    int row = blockIdx.x;
    const float* xr = x + (size_t)row * HIDD;
    __shared__ float red[256];
    float4 vals[2];
    float s = 0.f;
#pragma unroll
    for (int i = 0; i < 2; i++) {
        float4 v = *(const float4*)(xr + (threadIdx.x + i * 256) * 4);
        vals[i] = v;
        s += v.x * v.x + v.y * v.y + v.z * v.z + v.w * v.w;
    }
    red[threadIdx.x] = s;
    __syncthreads();
    for (int off = 128; off > 0; off >>= 1) {
        if (threadIdx.x < off) red[threadIdx.x] += red[threadIdx.x + off];
        __syncthreads();
    }
    float inv = rsqrtf(red[0] / (float)HIDD + 1e-6f);
#pragma unroll
    for (int i = 0; i < 2; i++) {
        int c = (threadIdx.x + i * 256) * 4;
        float4 v = vals[i];
        float4 wv = *(const float4*)(w + c);
        float4 o = make_float4(tf32rnd(v.x * inv * wv.x), tf32rnd(v.y * inv * wv.y),
                               tf32rnd(v.z * inv * wv.z), tf32rnd(v.w * inv * wv.w));
        *(float4*)(out + (size_t)row * HIDD + c) = o;
    }
}

// ---------------- RoPE (shared sin/cos table; fp angle formed in double) ----------------
__global__ void rope_kernel(float* __restrict__ qkv, const int* __restrict__ pos) {
    __shared__ float cs[64], sn[64];
    int tok = blockIdx.x;
    int p = pos[tok % SQ];
    if (threadIdx.x < 64) {
        double freq = exp(-(double)threadIdx.x * (9.210340371976184 / 64.0));
        float ang = (float)((double)p * freq);
        float s, c;
        sincosf(ang, &s, &c);
        cs[threadIdx.x] = c;
        sn[threadIdx.x] = s;
    }
    __syncthreads();
    for (int item = threadIdx.x; item < (NH + NKV) * 64; item += blockDim.x) {
        int head = item >> 6;
        int d = item & 63;
        float c = cs[d], s = sn[d];
        float* base = qkv + (size_t)tok * QKVD + head * HDIM;
        float t1 = base[d];
        float t2 = base[d + 64];
        base[d]      = t1 * c - t2 * s;
        base[d + 64] = t2 * c + t1 * s;
    }
}

// ---------------- Flash attention (fp32, causal, GQA); output tf32-rounded ----------------
__global__ void attn_kernel(const float* __restrict__ qkv, float* __restrict__ attn_out) {
    extern __shared__ float smem[];
    float* Qs = smem;
    float* Ks = Qs + 64 * APITCH;
    float* Vs = Ks + 64 * APITCH;
    float* Ps = Vs + 64 * APITCH;

    int qt = blockIdx.x, h = blockIdx.y, b = blockIdx.z;
    int kvh = h / (NH / NKV);
    int tid = threadIdx.x, w = tid / 32, lane = tid % 32;
    int tokQ0 = b * SQ + qt * 64;

    for (int i = tid; i < 64 * 32; i += 256) {
        int r = i / 32, c4 = (i % 32) * 4;
        *(float4*)(Qs + r * APITCH + c4) =
            *(const float4*)(qkv + (size_t)(tokQ0 + r) * QKVD + h * HDIM + c4);
    }

    float m[8], l[8], o[8][4];
#pragma unroll
    for (int r = 0; r < 8; r++) {
        m[r] = -1e30f; l[r] = 0.f;
        o[r][0] = o[r][1] = o[r][2] = o[r][3] = 0.f;
    }
    const float scale = 0.08838834764831845f;

    for (int kt = 0; kt <= qt; kt++) {
        __syncthreads();
        int tokK0 = b * SQ + kt * 64;
        for (int i = tid; i < 64 * 32; i += 256) {
            int r = i / 32, c4 = (i % 32) * 4;
            const float* base = qkv + (size_t)(tokK0 + r) * QKVD;
            *(float4*)(Ks + r * APITCH + c4) =
                *(const float4*)(base + NH * HDIM + kvh * HDIM + c4);
            *(float4*)(Vs + r * APITCH + c4) =
                *(const float4*)(base + (NH + NKV) * HDIM + kvh * HDIM + c4);
        }
        __syncthreads();

        bool diag = (kt == qt);
        for (int r = 0; r < 8; r++) {
            int qi = w * 8 + r;
            const float4* q4 = (const float4*)(Qs + qi * APITCH);
            const float4* k14 = (const float4*)(Ks + lane * APITCH);
            const float4* k24 = (const float4*)(Ks + (lane + 32) * APITCH);
            float s1 = 0.f, s2 = 0.f;
#pragma unroll 8
            for (int kk = 0; kk < 32; kk++) {
                float4 qv = q4[kk], a = k14[kk], c = k24[kk];
                s1 += qv.x * a.x + qv.y * a.y + qv.z * a.z + qv.w * a.w;
                s2 += qv.x * c.x + qv.y * c.y + qv.z * c.z + qv.w * c.w;
            }
            s1 *= scale; s2 *= scale;
            if (diag) {
                if (lane > qi) s1 = -1e30f;
                if (lane + 32 > qi) s2 = -1e30f;
            }
            float mx = fmaxf(s1, s2);
#pragma unroll
            for (int off = 16; off > 0; off >>= 1)
                mx = fmaxf(mx, __shfl_xor_sync(0xffffffffu, mx, off));
            float mnew = fmaxf(m[r], mx);
            float p1 = expf(s1 - mnew);
            float p2 = expf(s2 - mnew);
            float corr = expf(m[r] - mnew);
            float rowsum = p1 + p2;
#pragma unroll
            for (int off = 16; off > 0; off >>= 1)
                rowsum += __shfl_xor_sync(0xffffffffu, rowsum, off);
            l[r] = l[r] * corr + rowsum;
            m[r] = mnew;
            o[r][0] *= corr; o[r][1] *= corr; o[r][2] *= corr; o[r][3] *= corr;
            Ps[qi * 64 + lane] = p1;
            Ps[qi * 64 + lane + 32] = p2;
        }
        __syncwarp();
        for (int j = 0; j < 64; j++) {
            float4 v4 = *(const float4*)(Vs + j * APITCH + lane * 4);
#pragma unroll
            for (int r = 0; r < 8; r++) {
                float p = Ps[(w * 8 + r) * 64 + j];
                o[r][0] += p * v4.x; o[r][1] += p * v4.y;
                o[r][2] += p * v4.z; o[r][3] += p * v4.w;
            }
        }
    }

#pragma unroll
    for (int r = 0; r < 8; r++) {
        int qi = w * 8 + r;
        float inv = 1.f / l[r];
        float4 v = make_float4(tf32rnd(o[r][0] * inv), tf32rnd(o[r][1] * inv),
                               tf32rnd(o[r][2] * inv), tf32rnd(o[r][3] * inv));
        *(float4*)(attn_out + (size_t)(tokQ0 + qi) * HIDD + h * HDIM + lane * 4) = v;
    }
}

// ---------------- SiLU(gate) * up (output tf32-rounded) ----------------
__global__ void silu_kernel(const float* __restrict__ gu, float* __restrict__ act) {
    size_t n4 = (size_t)NTOK * INTD / 4;
    for (size_t idx = (size_t)blockIdx.x * blockDim.x + threadIdx.x; idx < n4;
         idx += (size_t)gridDim.x * blockDim.x) {
        size_t t = idx / (INTD / 4);
        size_t c = (idx % (INTD / 4)) * 4;
        float4 g = *(const float4*)(gu + t * (2 * INTD) + c);
        float4 u = *(const float4*)(gu + t * (2 * INTD) + INTD + c);
        float4 o;
        o.x = tf32rnd(g.x / (1.f + expf(-g.x)) * u.x);
        o.y = tf32rnd(g.y / (1.f + expf(-g.y)) * u.y);
        o.z = tf32rnd(g.z / (1.f + expf(-g.z)) * u.z);
        o.w = tf32rnd(g.w / (1.f + expf(-g.w)) * u.w);
        *(float4*)(act + idx * 4) = o;
    }
}

#define ATTN_SMEM ((3 * 64 * APITCH + 64 * 64) * 4)

extern "C" void kernel_launch(void* const* d_in, const int* in_sizes, int n_in,
                              void* d_out, int out_size) {
    const float* x    = (const float*)d_in[0];
    const float* ln1  = (const float*)d_in[1];
    const float* wqkv = (const float*)d_in[2];
    const float* wo   = (const float*)d_in[3];
    const float* ln2  = (const float*)d_in[4];
    const float* wgu  = (const float*)d_in[5];
    const float* wdn  = (const float*)d_in[6];
    const int*   pos  = (const int*)d_in[7];
    float* out = (float*)d_out;

    void *xn, *qkv, *attn, *h1, *h2, *gu, *act;
    void *wqkvT, *woT, *wguT, *wdnT;
    cudaGetSymbolAddress(&xn, g_xn);
    cudaGetSymbolAddress(&qkv, g_qkv);
    cudaGetSymbolAddress(&attn, g_attn);
    cudaGetSymbolAddress(&h1, g_h1);
    cudaGetSymbolAddress(&h2, g_h2);
    cudaGetSymbolAddress(&gu, g_gu);
    cudaGetSymbolAddress(&act, g_act);
    cudaGetSymbolAddress(&wqkvT, g_wqkvT);
    cudaGetSymbolAddress(&woT, g_woT);
    cudaGetSymbolAddress(&wguT, g_wguT);
    cudaGetSymbolAddress(&wdnT, g_wdnT);

    cudaFuncSetAttribute(attn_kernel, cudaFuncAttributeMaxDynamicSharedMemorySize, ATTN_SMEM);
    cudaFuncSetAttribute(tc_gemm<false>, cudaFuncAttributeMaxDynamicSharedMemorySize, GEMM_SMEM_TC);
    cudaFuncSetAttribute(tc_gemm<true>,  cudaFuncAttributeMaxDynamicSharedMemorySize, GEMM_SMEM_TC);

    // 0. weight transpose + tf32 rounding
    {
        dim3 b(32, 8);
        transpose_round_kernel<<<dim3(QKVD / 32, HIDD / 32), b>>>(wqkv, (float*)wqkvT, HIDD, QKVD);
        transpose_round_kernel<<<dim3(HIDD / 32, HIDD / 32), b>>>(wo, (float*)woT, HIDD, HIDD);
        transpose_round_kernel<<<dim3(2 * INTD / 32, HIDD / 32), b>>>(wgu, (float*)wguT, HIDD, 2 * INTD);
        transpose_round_kernel<<<dim3(HIDD / 32, INTD / 32), b>>>(wdn, (float*)wdnT, INTD, HIDD);
    }
    // 1. h = rmsnorm(x, ln1)  (tf32-rounded)
    rmsnorm_kernel<<<NTOK, 256>>>(x, ln1, (float*)xn);
    // 2. qkv = h @ wqkv
    tc_gemm<false><<<dim3(NTOK / TM, QKVD / TN), 256, GEMM_SMEM_TC>>>(
        (const float*)xn, (const float*)wqkvT, nullptr, (float*)qkv, QKVD, HIDD);
    // 3. RoPE on q,k
    rope_kernel<<<NTOK, 256>>>((float*)qkv, pos);
    // 4. attention (output tf32-rounded)
    {
        dim3 g(SQ / 64, NH, BATCH);
        attn_kernel<<<g, 256, ATTN_SMEM>>>((const float*)qkv, (float*)attn);
    }
    // 5. h1 = x + attn @ wo
    tc_gemm<true><<<dim3(NTOK / TM, HIDD / TN), 256, GEMM_SMEM_TC>>>(
        (const float*)attn, (const float*)woT, x, (float*)h1, HIDD, HIDD);
    // 6. h2 = rmsnorm(h1, ln2)  (tf32-rounded)
    rmsnorm_kernel<<<NTOK, 256>>>((const float*)h1, ln2, (float*)h2);
    // 7. gu = h2 @ w_gate_up
    tc_gemm<false><<<dim3(NTOK / TM, 2 * INTD / TN), 256, GEMM_SMEM_TC>>>(
        (const float*)h2, (const float*)wguT, nullptr, (float*)gu, 2 * INTD, HIDD);
    // 8. act = silu(gate)*up  (tf32-rounded)
    silu_kernel<<<2048, 256>>>((const float*)gu, (float*)act);
    // 9. out = h1 + act @ w_down
    tc_gemm<true><<<dim3(NTOK / TM, HIDD / TN), 256, GEMM_SMEM_TC>>>(
        (const float*)act, (const float*)wdnT, (const float*)h1, out, HIDD, INTD);
}